// round 4
// baseline (speedup 1.0000x reference)
#include <cuda_runtime.h>
#include <math.h>

#define BB 256
#define HH 512
#define H4 2048
#define LEN 48
#define LOOKN 10
#define K2H 1024
#define STARTI 48
#define LABW 58
#define NBLK 256
#define NTHR 128

// ---- scratch layout (single __device__ buffer) ----
constexpr size_t O_WISEQ = 0;
constexpr size_t O_MID2  = O_WISEQ + (size_t)BB*LEN*HH;
constexpr size_t O_Y     = O_MID2  + (size_t)BB*LEN*HH;
constexpr size_t O_HTCT  = O_Y     + (size_t)BB*LEN*HH;
constexpr size_t O_HECE  = O_HTCT  + (size_t)BB*K2H;
constexpr size_t O_HCMID = O_HECE  + (size_t)BB*K2H;
constexpr size_t O_DECIN = O_HCMID + (size_t)BB*K2H;
constexpr size_t O_WTWHO = O_DECIN + (size_t)BB*HH;
constexpr size_t O_TU    = O_WTWHO + (size_t)BB*K2H;
constexpr size_t O_SC    = O_TU    + (size_t)BB*HH;
constexpr size_t O_XM    = O_SC    + (size_t)BB*HH;
constexpr size_t O_GATES = O_XM    + (size_t)BB*HH;
constexpr size_t O_BTG   = O_GATES + (size_t)BB*H4;
constexpr size_t O_BSP   = O_BTG   + H4;
constexpr size_t O_BMID  = O_BSP   + H4;
constexpr size_t O_WTGC  = O_BMID  + H4;
constexpr size_t O_WTGX  = O_WTGC  + H4;
constexpr size_t O_WTWH  = O_WTGX  + (size_t)H4*HH;
constexpr size_t O_LAB   = O_WTWH  + (size_t)K2H*K2H;
constexpr size_t G_TOTAL = O_LAB + BB;

__device__ float g_buf[G_TOTAL];

// ---- global barrier state ----
__device__ unsigned g_arrive;
__device__ unsigned g_release;

__device__ __forceinline__ void gsync(unsigned ph)
{
    __syncthreads();
    if (threadIdx.x == 0) {
        __threadfence();   // release: make this block's writes visible (and CCTL.IVALL)
        unsigned arrived = atomicAdd(&g_arrive, 1u) + 1u;
        if (arrived == (unsigned)NBLK * ph) {
            atomicExch(&g_release, ph);
        } else {
            while (*(volatile unsigned*)&g_release < ph) { __nanosleep(64); }
        }
        __threadfence();   // acquire: invalidate L1D so post-barrier loads are fresh
    }
    __syncthreads();
}

struct Params {
    const float *inp, *labp;
    const float *Wih_sp, *Whh_sp, *Whh_tg, *Wih_md, *Whh_md;
    const float *Wi_w, *Wi_b, *We_w, *Vd_w, *Vd_b, *Wx_w, *Wx_b;
    const float *V_w, *V_b, *reg_w, *reg_b;
    float* out;
    float* gb;
};

// ---- fused GEMM tile loop: C = act(A1@W1^T + A2@W2^T + bias + add1 + add2 + u[m]*v[n]) ----
__device__ void gemm_dev(
    const float* __restrict__ A1, int lda1, const float* __restrict__ W1, int ldw1, int K1,
    const float* __restrict__ A2, int lda2, const float* __restrict__ W2, int ldw2, int K2,
    const float* __restrict__ bias,
    const float* __restrict__ add1, int ldad1,
    const float* __restrict__ add2, int ldad2,
    const float* __restrict__ r1u, const float* __restrict__ r1v,
    float* __restrict__ C, int M, int N, int dotanh,
    float (*As)[36], float (*Ws)[68])
{
    const int tid = threadIdx.x;
    const int ty = tid >> 4, tx = tid & 15;
    const int am = tid >> 2, ak = (tid & 3) * 4;
    const int wn = tid >> 2, wk = (tid & 3) * 4;
    const int nct = N >> 6;
    const int ntiles = (M >> 5) * nct;

    for (int t = blockIdx.x; t < ntiles; t += gridDim.x) {
        const int m0 = (t / nct) << 5;
        const int n0 = (t % nct) << 6;

        float acc[4][4];
#pragma unroll
        for (int i = 0; i < 4; i++)
#pragma unroll
            for (int j = 0; j < 4; j++) acc[i][j] = 0.f;

        for (int seg = 0; seg < 2; ++seg) {
            const float* A = seg ? A2 : A1;
            if (!A) continue;
            const float* W = seg ? W2 : W1;
            const int lda = seg ? lda2 : lda1;
            const int ldw = seg ? ldw2 : ldw1;
            const int K   = seg ? K2   : K1;

            float4 pa  = *(const float4*)(A + (size_t)(m0 + am) * lda + ak);
            float4 pw0 = *(const float4*)(W + (size_t)(n0 + wn) * ldw + wk);
            float4 pw1 = *(const float4*)(W + (size_t)(n0 + 32 + wn) * ldw + wk);

            for (int k0 = 0; k0 < K; k0 += 16) {
                __syncthreads();
                As[ak+0][am] = pa.x; As[ak+1][am] = pa.y; As[ak+2][am] = pa.z; As[ak+3][am] = pa.w;
                Ws[wk+0][wn] = pw0.x; Ws[wk+1][wn] = pw0.y; Ws[wk+2][wn] = pw0.z; Ws[wk+3][wn] = pw0.w;
                Ws[wk+0][32+wn] = pw1.x; Ws[wk+1][32+wn] = pw1.y; Ws[wk+2][32+wn] = pw1.z; Ws[wk+3][32+wn] = pw1.w;
                __syncthreads();
                const int kn = k0 + 16;
                if (kn < K) {
                    pa  = *(const float4*)(A + (size_t)(m0 + am) * lda + kn + ak);
                    pw0 = *(const float4*)(W + (size_t)(n0 + wn) * ldw + kn + wk);
                    pw1 = *(const float4*)(W + (size_t)(n0 + 32 + wn) * ldw + kn + wk);
                }
#pragma unroll
                for (int kk = 0; kk < 16; ++kk) {
                    const float4 a = *(const float4*)(&As[kk][ty << 2]);
                    const float4 w = *(const float4*)(&Ws[kk][tx << 2]);
                    acc[0][0] += a.x*w.x; acc[0][1] += a.x*w.y; acc[0][2] += a.x*w.z; acc[0][3] += a.x*w.w;
                    acc[1][0] += a.y*w.x; acc[1][1] += a.y*w.y; acc[1][2] += a.y*w.z; acc[1][3] += a.y*w.w;
                    acc[2][0] += a.z*w.x; acc[2][1] += a.z*w.y; acc[2][2] += a.z*w.z; acc[2][3] += a.z*w.w;
                    acc[3][0] += a.w*w.x; acc[3][1] += a.w*w.y; acc[3][2] += a.w*w.z; acc[3][3] += a.w*w.w;
                }
            }
        }
#pragma unroll
        for (int i = 0; i < 4; i++) {
            const int m = m0 + (ty << 2) + i;
#pragma unroll
            for (int j = 0; j < 4; j++) {
                const int n = n0 + (tx << 2) + j;
                float v = acc[i][j];
                if (bias) v += bias[n];
                if (add1) v += add1[(size_t)m * ldad1 + n];
                if (add2) v += add2[(size_t)m * ldad2 + n];
                if (r1u)  v += r1u[m] * r1v[n];
                if (dotanh) v = tanhf(v);
                C[(size_t)m * N + n] = v;
            }
        }
        __syncthreads();
    }
}

__device__ void lstm_dev(const float* __restrict__ gates, float* __restrict__ state,
                         float* __restrict__ hout, int hstride)
{
    for (int idx = blockIdx.x * NTHR + threadIdx.x; idx < BB * HH; idx += NBLK * NTHR) {
        const int b = idx >> 9, h = idx & 511;
        const float* g = gates + (size_t)b * H4;
        const float gi = g[h], gf = g[512+h], gg = g[1024+h], go = g[1536+h];
        const float c = state[(size_t)b * K2H + 512 + h];
        const float si = 1.f/(1.f+expf(-gi)), sf = 1.f/(1.f+expf(-gf)), so = 1.f/(1.f+expf(-go));
        const float c2 = sf * c + si * tanhf(gg);
        const float hn = so * tanhf(c2);
        state[(size_t)b * K2H + h] = hn;
        state[(size_t)b * K2H + 512 + h] = c2;
        if (hout) hout[(size_t)b * hstride + h] = hn;
    }
}

__device__ void softmax_dev(const float* __restrict__ sc, const float* __restrict__ x,
                            int t, float* __restrict__ xm, float* red)
{
    const int b = blockIdx.x, tid = threadIdx.x;
    const int lane = tid & 31, wid = tid >> 5;
    const float* sr = sc + (size_t)b * 512;
    float v0 = sr[tid], v1 = sr[tid+128], v2 = sr[tid+256], v3 = sr[tid+384];
    float m = fmaxf(fmaxf(v0, v1), fmaxf(v2, v3));
#pragma unroll
    for (int o = 16; o; o >>= 1) m = fmaxf(m, __shfl_xor_sync(0xffffffffu, m, o));
    if (lane == 0) red[wid] = m;
    __syncthreads();
    const float bm = fmaxf(fmaxf(red[0], red[1]), fmaxf(red[2], red[3]));
    __syncthreads();
    const float e0 = expf(v0-bm), e1 = expf(v1-bm), e2 = expf(v2-bm), e3 = expf(v3-bm);
    float s = e0 + e1 + e2 + e3;
#pragma unroll
    for (int o = 16; o; o >>= 1) s += __shfl_xor_sync(0xffffffffu, s, o);
    if (lane == 0) red[wid] = s;
    __syncthreads();
    const float inv = 1.f / (red[0] + red[1] + red[2] + red[3]);
    const float* xr = x + ((size_t)b * LEN + t) * 512;
    xm[(size_t)b*512 + tid]     = xr[tid]     * e0 * inv;
    xm[(size_t)b*512 + tid+128] = xr[tid+128] * e1 * inv;
    xm[(size_t)b*512 + tid+256] = xr[tid+256] * e2 * inv;
    xm[(size_t)b*512 + tid+384] = xr[tid+384] * e3 * inv;
    __syncthreads();
}

__device__ void dec_dev(const float* __restrict__ y, const float* __restrict__ wh,
                        const float* __restrict__ Vw, const float* __restrict__ Vb,
                        const float* __restrict__ mid2, float* __restrict__ decin,
                        float* ssc)
{
    const int b = blockIdx.x, tid = threadIdx.x;
    const int lane = tid & 31, wid = tid >> 5;
    for (int l = wid; l < LEN; l += 4) {
        const float* yr = y + ((size_t)b * LEN + l) * HH;
        float pv = 0.f;
        for (int h = lane; h < HH; h += 32)
            pv += tanhf(wh[(size_t)b * K2H + h] + yr[h]) * Vw[h];
#pragma unroll
        for (int o = 16; o; o >>= 1) pv += __shfl_xor_sync(0xffffffffu, pv, o);
        if (lane == 0) ssc[l] = pv + Vb[0];
    }
    __syncthreads();
    float a0 = 0.f, a1 = 0.f, a2 = 0.f, a3 = 0.f;
    for (int l = 0; l < LEN; l++) {
        const float s = ssc[l];
        const float* mr = mid2 + ((size_t)b * LEN + l) * HH;
        a0 += s * mr[tid];     a1 += s * mr[tid+128];
        a2 += s * mr[tid+256]; a3 += s * mr[tid+384];
    }
    decin[(size_t)b*HH + tid]     = a0;
    decin[(size_t)b*HH + tid+128] = a1;
    decin[(size_t)b*HH + tid+256] = a2;
    decin[(size_t)b*HH + tid+384] = a3;
    __syncthreads();
}

// ---- persistent mega kernel ----
__global__ __launch_bounds__(NTHR) void mega(Params p)
{
    __shared__ float As[16][36];
    __shared__ float Ws[16][68];
    __shared__ float red[4];
    __shared__ float ssc[LEN];

    float* gb    = p.gb;
    float* wiseq = gb + O_WISEQ;  float* mid2  = gb + O_MID2;
    float* ybuf  = gb + O_Y;      float* htct  = gb + O_HTCT;
    float* hece  = gb + O_HECE;   float* hcmid = gb + O_HCMID;
    float* decin = gb + O_DECIN;  float* wtwho = gb + O_WTWHO;
    float* tu    = gb + O_TU;     float* sc    = gb + O_SC;
    float* xm    = gb + O_XM;     float* gates = gb + O_GATES;
    float* btg   = gb + O_BTG;    float* bsp   = gb + O_BSP;
    float* bmid  = gb + O_BMID;   float* wtgc  = gb + O_WTGC;
    float* wtgx  = gb + O_WTGX;   float* wtwh  = gb + O_WTWH;
    float* lab   = gb + O_LAB;

    unsigned ph = 0;

    // wiseq = input @ Wi_w^T + Wi_b
    gemm_dev(p.inp, 512, p.Wi_w, 512, 512, nullptr, 0, nullptr, 0, 0,
             p.Wi_b, nullptr, 0, nullptr, 0, nullptr, nullptr,
             wiseq, BB*LEN, HH, 0, As, Ws);
    gsync(++ph);

    for (int k = 0; k < LOOKN; k++) {
        // tg gates = decin@wtgx^T + ht@Whh_tg^T + b_tg + lab*wtgc
        gemm_dev(decin, 512, wtgx, 512, 512, htct, K2H, p.Whh_tg, 512, 512,
                 btg, nullptr, 0, nullptr, 0, lab, wtgc, gates, BB, H4, 0, As, Ws);
        gsync(++ph);
        lstm_dev(gates, htct, nullptr, 0);
        gsync(++ph);
        // wtwh gemm (blocks 0-127) | target dot (block 128) | zero states (129-255)
        if (blockIdx.x < 128) {
            gemm_dev(htct, K2H, wtwh, K2H, K2H, nullptr, 0, nullptr, 0, 0,
                     nullptr, nullptr, 0, nullptr, 0, nullptr, nullptr,
                     wtwho, BB, K2H, 0, As, Ws);
        } else if (blockIdx.x == 128) {
            const int lane = threadIdx.x & 31, wid = threadIdx.x >> 5;
            for (int r = wid; r < BB; r += 4) {
                float s = 0.f;
                for (int h = lane; h < HH; h += 32)
                    s += htct[(size_t)r * K2H + h] * p.reg_w[h];
#pragma unroll
                for (int o = 16; o; o >>= 1) s += __shfl_xor_sync(0xffffffffu, s, o);
                if (lane == 0) {
                    const float tv = s + p.reg_b[0];
                    p.out[r * LOOKN + k] = tv;
                    lab[r] = tv;
                }
            }
        } else {
            const int base = (blockIdx.x - 129) * NTHR + threadIdx.x;
            for (int i = base; i < BB * K2H; i += 127 * NTHR) {
                hece[i] = 0.f;
                hcmid[i] = 0.f;
            }
        }
        gsync(++ph);

        for (int l = 0; l < LEN; l++) {
            // tu = tanh(hece@We^T + wi_x[l] + wt)
            gemm_dev(hece, K2H, p.We_w, K2H, K2H, nullptr, 0, nullptr, 0, 0,
                     nullptr, wiseq + (size_t)l * HH, LEN*HH, wtwho, K2H,
                     nullptr, nullptr, tu, BB, HH, 1, As, Ws);
            gsync(++ph);
            // sc = tu @ Vd^T + Vd_b
            gemm_dev(tu, 512, p.Vd_w, 512, 512, nullptr, 0, nullptr, 0, 0,
                     p.Vd_b, nullptr, 0, nullptr, 0, nullptr, nullptr,
                     sc, BB, HH, 0, As, Ws);
            gsync(++ph);
            softmax_dev(sc, p.inp, l, xm, red);
            gsync(++ph);
            // sp gates = xm@Wih_sp^T + he@Whh_sp^T + b_sp
            gemm_dev(xm, 512, p.Wih_sp, 512, 512, hece, K2H, p.Whh_sp, 512, 512,
                     bsp, nullptr, 0, nullptr, 0, nullptr, nullptr,
                     gates, BB, H4, 0, As, Ws);
            gsync(++ph);
            lstm_dev(gates, hece, nullptr, 0);
            gsync(++ph);
            // mid gates = he@Wih_mid^T + hmid@Whh_mid^T + b_mid
            gemm_dev(hece, K2H, p.Wih_md, 512, 512, hcmid, K2H, p.Whh_md, 512, 512,
                     bmid, nullptr, 0, nullptr, 0, nullptr, nullptr,
                     gates, BB, H4, 0, As, Ws);
            gsync(++ph);
            lstm_dev(gates, hcmid, mid2 + (size_t)l * HH, LEN*HH);
            gsync(++ph);
        }
        // y = mid2 @ Wx^T + Wx_b
        gemm_dev(mid2, 512, p.Wx_w, 512, 512, nullptr, 0, nullptr, 0, 0,
                 p.Wx_b, nullptr, 0, nullptr, 0, nullptr, nullptr,
                 ybuf, BB*LEN, HH, 0, As, Ws);
        gsync(++ph);
        dec_dev(ybuf, wtwho + 512, p.V_w, p.V_b, mid2, decin, ssc);
        gsync(++ph);
    }
}

// ---- prep: biases, Wih_tg repack, Wt|Wh stack ----
__global__ __launch_bounds__(256) void prep_k(
    const float* bihsp, const float* bhhsp, const float* bihtg, const float* bhhtg,
    const float* bihmid, const float* bhhmid, const float* wihtg,
    const float* wtw, const float* whw)
{
    const int i = blockIdx.x * 256 + threadIdx.x;
    if (i < H4) {
        g_buf[O_BSP + i]  = bihsp[i] + bhhsp[i];
        g_buf[O_BTG + i]  = bihtg[i] + bhhtg[i];
        g_buf[O_BMID + i] = bihmid[i] + bhhmid[i];
        g_buf[O_WTGC + i] = wihtg[(size_t)i * 513];
    }
    if (i < H4 * HH) {
        const int r = i >> 9, c = i & 511;
        g_buf[O_WTGX + i] = wihtg[(size_t)r * 513 + 1 + c];
    }
    if (i < K2H * K2H) {
        const int r = i >> 10, c = i & 1023;
        g_buf[O_WTWH + i] = (r < 512) ? wtw[(size_t)r * K2H + c]
                                      : whw[(size_t)(r - 512) * K2H + c];
    }
}

__global__ __launch_bounds__(256) void init_k(const float* __restrict__ labp)
{
    const int i = blockIdx.x * 256 + threadIdx.x;
    if (i == 0) { g_arrive = 0u; g_release = 0u; }
    if (i < BB * K2H) g_buf[O_HTCT + i] = 0.f;
    if (i < BB * HH)  g_buf[O_DECIN + i] = 0.f;
    if (i < BB)       g_buf[O_LAB + i] = labp[(size_t)i * LABW + STARTI];
}

extern "C" void kernel_launch(void* const* d_in, const int* in_sizes, int n_in,
                              void* d_out, int out_size)
{
    Params p;
    p.inp    = (const float*)d_in[0];
    p.labp   = (const float*)d_in[1];
    p.Wih_sp = (const float*)d_in[2];
    p.Whh_sp = (const float*)d_in[3];
    p.Whh_tg = (const float*)d_in[7];
    p.Wih_md = (const float*)d_in[10];
    p.Whh_md = (const float*)d_in[11];
    p.Wi_w   = (const float*)d_in[14];
    p.Wi_b   = (const float*)d_in[15];
    p.We_w   = (const float*)d_in[16];
    p.Vd_w   = (const float*)d_in[18];
    p.Vd_b   = (const float*)d_in[19];
    p.Wx_w   = (const float*)d_in[20];
    p.Wx_b   = (const float*)d_in[21];
    p.V_w    = (const float*)d_in[23];
    p.V_b    = (const float*)d_in[24];
    p.reg_w  = (const float*)d_in[25];
    p.reg_b  = (const float*)d_in[26];
    p.out    = (float*)d_out;

    float* gb = nullptr;
    cudaGetSymbolAddress((void**)&gb, g_buf);
    p.gb = gb;

    prep_k<<<(2 * K2H * K2H + 255) / 256, 256>>>(
        (const float*)d_in[4], (const float*)d_in[5], (const float*)d_in[8],
        (const float*)d_in[9], (const float*)d_in[12], (const float*)d_in[13],
        (const float*)d_in[6], (const float*)d_in[17], (const float*)d_in[22]);
    init_k<<<(BB * K2H + 255) / 256, 256>>>((const float*)d_in[1]);
    mega<<<NBLK, NTHR>>>(p);
}